// round 1
// baseline (speedup 1.0000x reference)
#include <cuda_runtime.h>

// Problem constants (fixed by the dataset)
#define T_STEPS 2048
#define BATCH   64
#define IDIM    512
#define HDIM    512

#define N_GROUPS 8            // groups of batch rows
#define BLKS_PER_GROUP 16     // blocks per group (each owns 32 H columns)
#define B_PER_GROUP 8         // batch rows per group
#define COLS_PER_BLK 32

typedef unsigned long long u64;

// ---------------- scratch (static device allocations; no cudaMalloc) -------
__device__ float g_xf[(long)T_STEPS * BATCH * HDIM];   // 268 MB
__device__ float g_xh[(long)T_STEPS * BATCH * HDIM];   // 268 MB
__device__ float g_hbuf[BATCH * HDIM];
__device__ float g_gbuf[BATCH * HDIM];
__device__ unsigned int g_cnt[N_GROUPS * 32];          // padded barrier counters

// ---------------- packed f32x2 helpers (sm_100+ packed fp32 pipe) ----------
__device__ __forceinline__ u64 pack2(float x, float y) {
    u64 r; asm("mov.b64 %0, {%1, %2};" : "=l"(r) : "f"(x), "f"(y)); return r;
}
__device__ __forceinline__ u64 ffma2(u64 a, u64 b, u64 c) {
    u64 d; asm("fma.rn.f32x2 %0, %1, %2, %3;" : "=l"(d) : "l"(a), "l"(b), "l"(c));
    return d;
}
__device__ __forceinline__ float2 unpack2(u64 a) {
    float2 r; asm("mov.b64 {%0, %1}, %2;" : "=f"(r.x), "=f"(r.y) : "l"(a)); return r;
}

// ---------------- release/acquire barrier primitives ------------------------
__device__ __forceinline__ void bar_arrive(unsigned int* p) {
    asm volatile("red.release.gpu.global.add.u32 [%0], 1;" :: "l"(p) : "memory");
}
__device__ __forceinline__ unsigned int ld_acq(const unsigned int* p) {
    unsigned int v;
    asm volatile("ld.acquire.gpu.global.u32 %0, [%1];" : "=r"(v) : "l"(p) : "memory");
    return v;
}

__global__ void init_kernel() {
    if (threadIdx.x < N_GROUPS) g_cnt[threadIdx.x * 32] = 0u;
}

// ============================================================================
// Phase 1: xf = x @ Wx_f^T + b_f ; xh = x @ Wx_h^T + b_h
// Tiled fp32 GEMM, BM=128 BN=64 BK=16, 256 threads, 8x4 per thread,
// f32x2-packed accumulation along M.
// ============================================================================
__global__ __launch_bounds__(256) void proj_kernel(
    const float* __restrict__ X,
    const float* __restrict__ Wf, const float* __restrict__ bf,
    const float* __restrict__ Wh, const float* __restrict__ bh)
{
    const float* W  = blockIdx.z ? Wh : Wf;
    const float* bv = blockIdx.z ? bh : bf;
    float* out = blockIdx.z ? g_xh : g_xf;

    __shared__ float As[16][132];   // A transposed: As[k][m]
    __shared__ float Bs[16][68];    // B transposed: Bs[k][n]

    const int tid = threadIdx.x;
    const int tx = tid & 15;        // 16 column-groups of 4
    const int ty = tid >> 4;        // 16 row-groups of 8
    const long m0 = (long)blockIdx.x * 128;
    const int  n0 = blockIdx.y * 64;

    u64 acc[4][4];
    #pragma unroll
    for (int p = 0; p < 4; p++)
        #pragma unroll
        for (int c = 0; c < 4; c++) acc[p][c] = 0ull;

    for (int k0 = 0; k0 < IDIM; k0 += 16) {
        // load A tile: 128x16 = 512 float4
        #pragma unroll
        for (int q0 = 0; q0 < 2; q0++) {
            int q = tid + q0 * 256;
            int row = q >> 2;
            int kc  = (q & 3) * 4;
            float4 v = *(const float4*)&X[(m0 + row) * IDIM + k0 + kc];
            As[kc+0][row] = v.x; As[kc+1][row] = v.y;
            As[kc+2][row] = v.z; As[kc+3][row] = v.w;
        }
        // load B tile: 64x16 = 256 float4
        {
            int row = tid >> 2;
            int kc  = (tid & 3) * 4;
            float4 v = *(const float4*)&W[(n0 + row) * IDIM + k0 + kc];
            Bs[kc+0][row] = v.x; Bs[kc+1][row] = v.y;
            Bs[kc+2][row] = v.z; Bs[kc+3][row] = v.w;
        }
        __syncthreads();

        #pragma unroll
        for (int kk = 0; kk < 16; kk++) {
            float4 a0 = *(const float4*)&As[kk][ty * 8];
            float4 a1 = *(const float4*)&As[kk][ty * 8 + 4];
            float4 b4 = *(const float4*)&Bs[kk][tx * 4];
            u64 a2[4] = { pack2(a0.x, a0.y), pack2(a0.z, a0.w),
                          pack2(a1.x, a1.y), pack2(a1.z, a1.w) };
            u64 bb[4] = { pack2(b4.x, b4.x), pack2(b4.y, b4.y),
                          pack2(b4.z, b4.z), pack2(b4.w, b4.w) };
            #pragma unroll
            for (int p = 0; p < 4; p++)
                #pragma unroll
                for (int c = 0; c < 4; c++)
                    acc[p][c] = ffma2(a2[p], bb[c], acc[p][c]);
        }
        __syncthreads();
    }

    float4 bias4 = *(const float4*)&bv[n0 + tx * 4];
    #pragma unroll
    for (int p = 0; p < 4; p++) {
        float2 c0 = unpack2(acc[p][0]);
        float2 c1 = unpack2(acc[p][1]);
        float2 c2 = unpack2(acc[p][2]);
        float2 c3 = unpack2(acc[p][3]);
        long mlo = m0 + ty * 8 + 2 * p;
        float4 lo = make_float4(c0.x + bias4.x, c1.x + bias4.y,
                                c2.x + bias4.z, c3.x + bias4.w);
        float4 hi = make_float4(c0.y + bias4.x, c1.y + bias4.y,
                                c2.y + bias4.z, c3.y + bias4.w);
        *(float4*)&out[mlo * HDIM + n0 + tx * 4]       = lo;
        *(float4*)&out[(mlo + 1) * HDIM + n0 + tx * 4] = hi;
    }
}

// ============================================================================
// Phase 2: persistent recurrent scan.
// 128 blocks = 8 groups x 16 blocks. Group owns 8 batch rows; block owns
// 32 H columns with its Wh_f/Wh_h slices resident in SMEM for all steps.
// Per step: GEMM-A (f gate) -> group barrier -> GEMM-B (candidate+blend)
// -> group barrier -> reload h.
// ============================================================================
#define WPAD 514                                  // padded W row (floats)
#define SCAN_SMEM ((2*32*WPAD + 8*512 + 8*512 + 8*8*32 + 8*32) * 4)

__device__ __forceinline__ float sigmoid_f(float x) {
    return 1.0f / (1.0f + __expf(-x));
}
__device__ __forceinline__ float tanh_f(float x) {
    // tanh(x) = 1 - 2/(e^{2x}+1); saturates correctly for |x| large
    return 1.0f - 2.0f / (__expf(2.0f * x) + 1.0f);
}

__global__ __launch_bounds__(256, 1) void scan_kernel(
    const float* __restrict__ h0,
    const float* __restrict__ Whf,
    const float* __restrict__ Whh,
    float* __restrict__ out)
{
    extern __shared__ float smem[];
    float* Wf_s  = smem;                      // 32 x 514
    float* Wh_s  = Wf_s + 32 * WPAD;          // 32 x 514
    float* h_s   = Wh_s + 32 * WPAD;          // 8 x 512
    float* g_s   = h_s + 8 * 512;             // 8 x 512
    float* part  = g_s + 8 * 512;             // [b][ks][j] 8*8*32
    float* f_s   = part + 8 * 8 * 32;         // 8 x 32

    const int tid = threadIdx.x;
    const int grp = blockIdx.x >> 4;
    const int blk = blockIdx.x & 15;
    const int j0  = blk * COLS_PER_BLK;
    const int b0  = grp * B_PER_GROUP;

    // GEMM mapping: thread = (j in 0..31, ks in 0..7), k-slice of 64
    const int j  = tid & 31;
    const int ks = tid >> 5;
    // finalize mapping: thread = (fb in 0..7, fj in 0..31)
    const int fb = tid >> 5;
    const int fj = tid & 31;

    // load resident weight slices (rows j0..j0+31)
    for (int i = tid; i < 32 * 512; i += 256) {
        int r = i >> 9, c = i & 511;
        Wf_s[r * WPAD + c] = Whf[(j0 + r) * HDIM + c];
        Wh_s[r * WPAD + c] = Whh[(j0 + r) * HDIM + c];
    }
    // load initial h rows (full 512 cols for our 8 batch rows)
    {
        const float4* src = (const float4*)&h0[b0 * HDIM];
        float4* dst = (float4*)h_s;
        for (int i = tid; i < (8 * 512) / 4; i += 256) dst[i] = src[i];
    }
    __syncthreads();

    unsigned int* cntp = &g_cnt[grp * 32];
    unsigned int target = 0;

    const int kb = ks * 64;

    for (int t = 0; t < T_STEPS; t++) {
        // prefetch this step's xf/xh element (finalize mapping)
        const long xbase = (long)t * (BATCH * HDIM) + (long)(b0 + fb) * HDIM + j0 + fj;
        const float xf_v = g_xf[xbase];
        const float xh_v = g_xh[xbase];

        // ---------------- Phase A: partial f-GEMM over k-slice --------------
        {
            u64 acc[8];
            #pragma unroll
            for (int b = 0; b < 8; b++) acc[b] = 0ull;
            #pragma unroll 16
            for (int kk = 0; kk < 32; kk++) {
                const int k = kb + kk * 2;
                u64 w2 = *(const u64*)&Wf_s[j * WPAD + k];
                #pragma unroll
                for (int b = 0; b < 8; b++) {
                    u64 h2 = *(const u64*)&h_s[b * 512 + k];
                    acc[b] = ffma2(w2, h2, acc[b]);
                }
            }
            #pragma unroll
            for (int b = 0; b < 8; b++) {
                float2 a = unpack2(acc[b]);
                part[(b * 8 + ks) * 32 + j] = a.x + a.y;
            }
        }
        __syncthreads();
        // finalize A: f gate, g = f*h, publish g slice
        {
            float s = xf_v;
            #pragma unroll
            for (int q = 0; q < 8; q++) s += part[(fb * 8 + q) * 32 + fj];
            float f = sigmoid_f(s);
            f_s[fb * 32 + fj] = f;
            float g = f * h_s[fb * 512 + j0 + fj];
            g_gbuf[(b0 + fb) * HDIM + j0 + fj] = g;
        }
        // ---- group barrier 1 ----
        __syncthreads();
        if (tid == 0) {
            bar_arrive(cntp);
            target += BLKS_PER_GROUP;
            while (ld_acq(cntp) < target) { }
        } else {
            target += BLKS_PER_GROUP;
        }
        __syncthreads();

        // gather full g rows for the group
        {
            const float4* src = (const float4*)&g_gbuf[b0 * HDIM];
            float4* dst = (float4*)g_s;
            for (int i = tid; i < (8 * 512) / 4; i += 256) dst[i] = src[i];
        }
        __syncthreads();

        // ---------------- Phase B: partial candidate GEMM --------------------
        {
            u64 acc[8];
            #pragma unroll
            for (int b = 0; b < 8; b++) acc[b] = 0ull;
            #pragma unroll 16
            for (int kk = 0; kk < 32; kk++) {
                const int k = kb + kk * 2;
                u64 w2 = *(const u64*)&Wh_s[j * WPAD + k];
                #pragma unroll
                for (int b = 0; b < 8; b++) {
                    u64 g2 = *(const u64*)&g_s[b * 512 + k];
                    acc[b] = ffma2(w2, g2, acc[b]);
                }
            }
            #pragma unroll
            for (int b = 0; b < 8; b++) {
                float2 a = unpack2(acc[b]);
                part[(b * 8 + ks) * 32 + j] = a.x + a.y;
            }
        }
        __syncthreads();
        // finalize B: candidate, blend, emit y and new h
        {
            float s = xh_v;
            #pragma unroll
            for (int q = 0; q < 8; q++) s += part[(fb * 8 + q) * 32 + fj];
            float ht = tanh_f(s);
            float f  = f_s[fb * 32 + fj];
            float hp = h_s[fb * 512 + j0 + fj];
            float hn = fmaf(f, ht - hp, hp);            // (1-f)h + f*ht
            out[((long)t * BATCH + (b0 + fb)) * HDIM + j0 + fj] = hn;
            g_hbuf[(b0 + fb) * HDIM + j0 + fj] = hn;
            if (t == T_STEPS - 1) {
                out[(long)T_STEPS * BATCH * HDIM + (b0 + fb) * HDIM + j0 + fj] = hn;
            }
        }
        // ---- group barrier 2 ----
        __syncthreads();
        if (tid == 0) {
            bar_arrive(cntp);
            target += BLKS_PER_GROUP;
            while (ld_acq(cntp) < target) { }
        } else {
            target += BLKS_PER_GROUP;
        }
        __syncthreads();

        // reload full updated h rows
        {
            const float4* src = (const float4*)&g_hbuf[b0 * HDIM];
            float4* dst = (float4*)h_s;
            for (int i = tid; i < (8 * 512) / 4; i += 256) dst[i] = src[i];
        }
        __syncthreads();
    }
}

// ============================================================================
extern "C" void kernel_launch(void* const* d_in, const int* in_sizes, int n_in,
                              void* d_out, int out_size)
{
    const float* x   = (const float*)d_in[0];   // [T,B,I]
    const float* h0  = (const float*)d_in[1];   // [B,H]
    const float* Wxf = (const float*)d_in[2];   // [H,I]
    const float* Whf = (const float*)d_in[3];   // [H,H]
    const float* bf  = (const float*)d_in[4];   // [H]
    const float* Wxh = (const float*)d_in[5];   // [H,I]
    const float* Whh = (const float*)d_in[6];   // [H,H]
    const float* bh  = (const float*)d_in[7];   // [H]
    float* out = (float*)d_out;                 // y_seq then h_final

    cudaFuncSetAttribute(scan_kernel,
                         cudaFuncAttributeMaxDynamicSharedMemorySize, SCAN_SMEM);

    init_kernel<<<1, 32>>>();

    dim3 pgrid((T_STEPS * BATCH) / 128, HDIM / 64, 2);
    proj_kernel<<<pgrid, 256>>>(x, Wxf, bf, Wxh, bh);

    scan_kernel<<<N_GROUPS * BLKS_PER_GROUP, 256, SCAN_SMEM>>>(h0, Whf, Whh, out);
}

// round 2
// speedup vs baseline: 1.0869x; 1.0869x over previous
#include <cuda_runtime.h>

// Problem constants (fixed by the dataset)
#define T_STEPS 2048
#define BATCH   64
#define IDIM    512
#define HDIM    512

#define N_GROUPS 8            // groups of batch rows
#define BLKS_PER_GROUP 16     // blocks per group (each owns 32 H columns)
#define B_PER_GROUP 8         // batch rows per group
#define COLS_PER_BLK 32

typedef unsigned long long u64;

// ---------------- scratch (static device allocations; no cudaMalloc) -------
__device__ float g_xf[(long)T_STEPS * BATCH * HDIM];   // 268 MB
__device__ float g_xh[(long)T_STEPS * BATCH * HDIM];   // 268 MB
__device__ float g_hbuf[BATCH * HDIM];
__device__ float g_gbuf[BATCH * HDIM];
__device__ unsigned int g_cnt[N_GROUPS * 32];          // padded barrier counters

// ---------------- packed f32x2 helpers (sm_100+ packed fp32 pipe) ----------
__device__ __forceinline__ u64 pack2(float x, float y) {
    u64 r; asm("mov.b64 %0, {%1, %2};" : "=l"(r) : "f"(x), "f"(y)); return r;
}
__device__ __forceinline__ u64 ffma2(u64 a, u64 b, u64 c) {
    u64 d; asm("fma.rn.f32x2 %0, %1, %2, %3;" : "=l"(d) : "l"(a), "l"(b), "l"(c));
    return d;
}
__device__ __forceinline__ float2 unpack2(u64 a) {
    float2 r; asm("mov.b64 {%0, %1}, %2;" : "=f"(r.x), "=f"(r.y) : "l"(a)); return r;
}

// ---------------- L1-bypass global load (exchange must not hit stale L1) ---
__device__ __forceinline__ float4 ldcg4(const float4* p) {
    float4 v;
    asm volatile("ld.global.cg.v4.f32 {%0,%1,%2,%3}, [%4];"
                 : "=f"(v.x), "=f"(v.y), "=f"(v.z), "=f"(v.w) : "l"(p));
    return v;
}

// ---------------- release/acquire barrier primitives ------------------------
__device__ __forceinline__ void bar_arrive(unsigned int* p) {
    asm volatile("red.release.gpu.global.add.u32 [%0], 1;" :: "l"(p) : "memory");
}
__device__ __forceinline__ unsigned int ld_acq(const unsigned int* p) {
    unsigned int v;
    asm volatile("ld.acquire.gpu.global.u32 %0, [%1];" : "=r"(v) : "l"(p) : "memory");
    return v;
}

// ============================================================================
// Phase 1: xf = x @ Wx_f^T + b_f ; xh = x @ Wx_h^T + b_h
// Tiled fp32 GEMM, BM=128 BN=64 BK=16, 256 threads, 8x4 per thread,
// f32x2-packed accumulation along M. Also resets the scan barrier counters
// (block (0,0,0)) so the launch sequence is exactly 2 kernels.
// ============================================================================
__global__ __launch_bounds__(256) void proj_kernel(
    const float* __restrict__ X,
    const float* __restrict__ Wf, const float* __restrict__ bf,
    const float* __restrict__ Wh, const float* __restrict__ bh)
{
    if (blockIdx.x == 0 && blockIdx.y == 0 && blockIdx.z == 0 && threadIdx.x < N_GROUPS)
        g_cnt[threadIdx.x * 32] = 0u;

    const float* W  = blockIdx.z ? Wh : Wf;
    const float* bv = blockIdx.z ? bh : bf;
    float* out = blockIdx.z ? g_xh : g_xf;

    __shared__ float As[16][132];   // A transposed: As[k][m]
    __shared__ float Bs[16][68];    // B transposed: Bs[k][n]

    const int tid = threadIdx.x;
    const int tx = tid & 15;        // 16 column-groups of 4
    const int ty = tid >> 4;        // 16 row-groups of 8
    const long m0 = (long)blockIdx.x * 128;
    const int  n0 = blockIdx.y * 64;

    u64 acc[4][4];
    #pragma unroll
    for (int p = 0; p < 4; p++)
        #pragma unroll
        for (int c = 0; c < 4; c++) acc[p][c] = 0ull;

    for (int k0 = 0; k0 < IDIM; k0 += 16) {
        // load A tile: 128x16 = 512 float4
        #pragma unroll
        for (int q0 = 0; q0 < 2; q0++) {
            int q = tid + q0 * 256;
            int row = q >> 2;
            int kc  = (q & 3) * 4;
            float4 v = *(const float4*)&X[(m0 + row) * IDIM + k0 + kc];
            As[kc+0][row] = v.x; As[kc+1][row] = v.y;
            As[kc+2][row] = v.z; As[kc+3][row] = v.w;
        }
        // load B tile: 64x16 = 256 float4
        {
            int row = tid >> 2;
            int kc  = (tid & 3) * 4;
            float4 v = *(const float4*)&W[(n0 + row) * IDIM + k0 + kc];
            Bs[kc+0][row] = v.x; Bs[kc+1][row] = v.y;
            Bs[kc+2][row] = v.z; Bs[kc+3][row] = v.w;
        }
        __syncthreads();

        #pragma unroll
        for (int kk = 0; kk < 16; kk++) {
            float4 a0 = *(const float4*)&As[kk][ty * 8];
            float4 a1 = *(const float4*)&As[kk][ty * 8 + 4];
            float4 b4 = *(const float4*)&Bs[kk][tx * 4];
            u64 a2[4] = { pack2(a0.x, a0.y), pack2(a0.z, a0.w),
                          pack2(a1.x, a1.y), pack2(a1.z, a1.w) };
            u64 bb[4] = { pack2(b4.x, b4.x), pack2(b4.y, b4.y),
                          pack2(b4.z, b4.z), pack2(b4.w, b4.w) };
            #pragma unroll
            for (int p = 0; p < 4; p++)
                #pragma unroll
                for (int c = 0; c < 4; c++)
                    acc[p][c] = ffma2(a2[p], bb[c], acc[p][c]);
        }
        __syncthreads();
    }

    float4 bias4 = *(const float4*)&bv[n0 + tx * 4];
    #pragma unroll
    for (int p = 0; p < 4; p++) {
        float2 c0 = unpack2(acc[p][0]);
        float2 c1 = unpack2(acc[p][1]);
        float2 c2 = unpack2(acc[p][2]);
        float2 c3 = unpack2(acc[p][3]);
        long mlo = m0 + ty * 8 + 2 * p;
        float4 lo = make_float4(c0.x + bias4.x, c1.x + bias4.y,
                                c2.x + bias4.z, c3.x + bias4.w);
        float4 hi = make_float4(c0.y + bias4.x, c1.y + bias4.y,
                                c2.y + bias4.z, c3.y + bias4.w);
        *(float4*)&out[mlo * HDIM + n0 + tx * 4]       = lo;
        *(float4*)&out[(mlo + 1) * HDIM + n0 + tx * 4] = hi;
    }
}

// ============================================================================
// Phase 2: persistent recurrent scan.
// 128 blocks = 8 groups x 16 blocks. Group owns 8 batch rows; block owns
// 32 H columns with its Wh_f/Wh_h slices resident in SMEM for all steps.
// GEMM phases now use float4 (LDS.128) loads: h-broadcast wavefronts halved,
// LDS issue count halved vs Round-1 (crossbar-bound: ~1536 wf/phase).
// ============================================================================
#define WPAD 516                                  // padded W row (floats, %4==0)
#define SCAN_SMEM ((2*32*WPAD + 8*512 + 8*512 + 8*8*32 + 8*32) * 4)

__device__ __forceinline__ float sigmoid_f(float x) {
    return 1.0f / (1.0f + __expf(-x));
}
__device__ __forceinline__ float tanh_f(float x) {
    return 1.0f - 2.0f / (__expf(2.0f * x) + 1.0f);
}

__global__ __launch_bounds__(256, 1) void scan_kernel(
    const float* __restrict__ h0,
    const float* __restrict__ Whf,
    const float* __restrict__ Whh,
    float* __restrict__ out)
{
    extern __shared__ float smem[];
    float* Wf_s  = smem;                      // 32 x 516
    float* Wh_s  = Wf_s + 32 * WPAD;          // 32 x 516
    float* h_s   = Wh_s + 32 * WPAD;          // 8 x 512
    float* g_s   = h_s + 8 * 512;             // 8 x 512
    float* part  = g_s + 8 * 512;             // [b][ks][j] 8*8*32
    float* f_s   = part + 8 * 8 * 32;         // 8 x 32

    const int tid = threadIdx.x;
    const int grp = blockIdx.x >> 4;
    const int blk = blockIdx.x & 15;
    const int j0  = blk * COLS_PER_BLK;
    const int b0  = grp * B_PER_GROUP;

    // GEMM mapping: thread = (j in 0..31 = lane, ks in 0..7 = warp), k-slice 64
    const int j  = tid & 31;
    const int ks = tid >> 5;
    // finalize mapping: thread = (fb in 0..7, fj in 0..31)
    const int fb = tid >> 5;
    const int fj = tid & 31;

    // load resident weight slices (rows j0..j0+31)
    for (int i = tid; i < 32 * 512; i += 256) {
        int r = i >> 9, c = i & 511;
        Wf_s[r * WPAD + c] = Whf[(j0 + r) * HDIM + c];
        Wh_s[r * WPAD + c] = Whh[(j0 + r) * HDIM + c];
    }
    // load initial h rows (full 512 cols for our 8 batch rows)
    {
        const float4* src = (const float4*)&h0[b0 * HDIM];
        float4* dst = (float4*)h_s;
        for (int i = tid; i < (8 * 512) / 4; i += 256) dst[i] = src[i];
    }
    __syncthreads();

    unsigned int* cntp = &g_cnt[grp * 32];
    unsigned int target = 0;

    const int kb = ks * 64;
    const float* wfrow = &Wf_s[j * WPAD + kb];
    const float* whrow = &Wh_s[j * WPAD + kb];

    for (int t = 0; t < T_STEPS; t++) {
        // prefetch this step's xf/xh element (finalize mapping), streaming
        const long xbase = (long)t * (BATCH * HDIM) + (long)(b0 + fb) * HDIM + j0 + fj;
        const float xf_v = __ldcs(&g_xf[xbase]);
        const float xh_v = __ldcs(&g_xh[xbase]);

        // ---------------- Phase A: partial f-GEMM over k-slice --------------
        {
            u64 acc[8];
            #pragma unroll
            for (int b = 0; b < 8; b++) acc[b] = 0ull;
            #pragma unroll
            for (int i = 0; i < 16; i++) {
                float4 w4 = *(const float4*)(wfrow + 4 * i);
                u64 wlo = pack2(w4.x, w4.y);
                u64 whi = pack2(w4.z, w4.w);
                #pragma unroll
                for (int b = 0; b < 8; b++) {
                    float4 h4 = *(const float4*)&h_s[b * 512 + kb + 4 * i];
                    acc[b] = ffma2(wlo, pack2(h4.x, h4.y), acc[b]);
                    acc[b] = ffma2(whi, pack2(h4.z, h4.w), acc[b]);
                }
            }
            #pragma unroll
            for (int b = 0; b < 8; b++) {
                float2 a = unpack2(acc[b]);
                part[(b * 8 + ks) * 32 + j] = a.x + a.y;
            }
        }
        __syncthreads();
        // finalize A: f gate, g = f*h, publish g slice
        {
            float s = xf_v;
            #pragma unroll
            for (int q = 0; q < 8; q++) s += part[(fb * 8 + q) * 32 + fj];
            float f = sigmoid_f(s);
            f_s[fb * 32 + fj] = f;
            float g = f * h_s[fb * 512 + j0 + fj];
            g_gbuf[(b0 + fb) * HDIM + j0 + fj] = g;
        }
        // ---- group barrier 1 ----
        __syncthreads();
        if (tid == 0) {
            bar_arrive(cntp);
            target += BLKS_PER_GROUP;
            while (ld_acq(cntp) < target) { }
        } else {
            target += BLKS_PER_GROUP;
        }
        __syncthreads();

        // gather full g rows for the group (L1-bypassed: data from other SMs)
        {
            const float4* src = (const float4*)&g_gbuf[b0 * HDIM];
            float4* dst = (float4*)g_s;
            #pragma unroll
            for (int q = 0; q < 4; q++) dst[tid + q * 256] = ldcg4(&src[tid + q * 256]);
        }
        __syncthreads();

        // ---------------- Phase B: partial candidate GEMM --------------------
        {
            u64 acc[8];
            #pragma unroll
            for (int b = 0; b < 8; b++) acc[b] = 0ull;
            #pragma unroll
            for (int i = 0; i < 16; i++) {
                float4 w4 = *(const float4*)(whrow + 4 * i);
                u64 wlo = pack2(w4.x, w4.y);
                u64 whi = pack2(w4.z, w4.w);
                #pragma unroll
                for (int b = 0; b < 8; b++) {
                    float4 g4 = *(const float4*)&g_s[b * 512 + kb + 4 * i];
                    acc[b] = ffma2(wlo, pack2(g4.x, g4.y), acc[b]);
                    acc[b] = ffma2(whi, pack2(g4.z, g4.w), acc[b]);
                }
            }
            #pragma unroll
            for (int b = 0; b < 8; b++) {
                float2 a = unpack2(acc[b]);
                part[(b * 8 + ks) * 32 + j] = a.x + a.y;
            }
        }
        __syncthreads();
        // finalize B: candidate, blend, emit y and new h
        {
            float s = xh_v;
            #pragma unroll
            for (int q = 0; q < 8; q++) s += part[(fb * 8 + q) * 32 + fj];
            float ht = tanh_f(s);
            float f  = f_s[fb * 32 + fj];
            float hp = h_s[fb * 512 + j0 + fj];
            float hn = fmaf(f, ht - hp, hp);            // (1-f)h + f*ht
            out[((long)t * BATCH + (b0 + fb)) * HDIM + j0 + fj] = hn;
            g_hbuf[(b0 + fb) * HDIM + j0 + fj] = hn;
            if (t == T_STEPS - 1) {
                out[(long)T_STEPS * BATCH * HDIM + (b0 + fb) * HDIM + j0 + fj] = hn;
            }
        }
        // ---- group barrier 2 ----
        __syncthreads();
        if (tid == 0) {
            bar_arrive(cntp);
            target += BLKS_PER_GROUP;
            while (ld_acq(cntp) < target) { }
        } else {
            target += BLKS_PER_GROUP;
        }
        __syncthreads();

        // reload full updated h rows (L1-bypassed)
        {
            const float4* src = (const float4*)&g_hbuf[b0 * HDIM];
            float4* dst = (float4*)h_s;
            #pragma unroll
            for (int q = 0; q < 4; q++) dst[tid + q * 256] = ldcg4(&src[tid + q * 256]);
        }
        __syncthreads();
    }
}

// ============================================================================
extern "C" void kernel_launch(void* const* d_in, const int* in_sizes, int n_in,
                              void* d_out, int out_size)
{
    const float* x   = (const float*)d_in[0];   // [T,B,I]
    const float* h0  = (const float*)d_in[1];   // [B,H]
    const float* Wxf = (const float*)d_in[2];   // [H,I]
    const float* Whf = (const float*)d_in[3];   // [H,H]
    const float* bf  = (const float*)d_in[4];   // [H]
    const float* Wxh = (const float*)d_in[5];   // [H,I]
    const float* Whh = (const float*)d_in[6];   // [H,H]
    const float* bh  = (const float*)d_in[7];   // [H]
    float* out = (float*)d_out;                 // y_seq then h_final

    cudaFuncSetAttribute(scan_kernel,
                         cudaFuncAttributeMaxDynamicSharedMemorySize, SCAN_SMEM);

    dim3 pgrid((T_STEPS * BATCH) / 128, HDIM / 64, 2);
    proj_kernel<<<pgrid, 256>>>(x, Wxf, bf, Wxh, bh);

    scan_kernel<<<N_GROUPS * BLKS_PER_GROUP, 256, SCAN_SMEM>>>(h0, Whf, Whh, out);
}

// round 3
// speedup vs baseline: 1.0916x; 1.0044x over previous
#include <cuda_runtime.h>
#include <cstdint>

// Problem constants (fixed by the dataset)
#define T_STEPS 2048
#define BATCH   64
#define IDIM    512
#define HDIM    512

#define N_GROUPS 8
#define BLKS_PER_GROUP 16
#define B_PER_GROUP 8
#define COLS_PER_BLK 32

typedef unsigned long long u64;

// ---------------- scratch (static device allocations; no cudaMalloc) -------
__device__ float g_xf[(long)T_STEPS * BATCH * HDIM];   // 268 MB
__device__ float g_xh[(long)T_STEPS * BATCH * HDIM];   // 268 MB
__device__ float g_hbuf[BATCH * HDIM];                 // fallback path
__device__ float g_gbuf[BATCH * HDIM];                 // fallback path
__device__ unsigned int g_cnt[N_GROUPS * 32];          // fallback barrier counters

// ---------------- packed f32x2 helpers --------------------------------------
__device__ __forceinline__ u64 pack2(float x, float y) {
    u64 r; asm("mov.b64 %0, {%1, %2};" : "=l"(r) : "f"(x), "f"(y)); return r;
}
__device__ __forceinline__ u64 ffma2(u64 a, u64 b, u64 c) {
    u64 d; asm("fma.rn.f32x2 %0, %1, %2, %3;" : "=l"(d) : "l"(a), "l"(b), "l"(c));
    return d;
}
__device__ __forceinline__ float2 unpack2(u64 a) {
    float2 r; asm("mov.b64 {%0, %1}, %2;" : "=f"(r.x), "=f"(r.y) : "l"(a)); return r;
}

__device__ __forceinline__ float4 ldcg4(const float4* p) {
    float4 v;
    asm volatile("ld.global.cg.v4.f32 {%0,%1,%2,%3}, [%4];"
                 : "=f"(v.x), "=f"(v.y), "=f"(v.z), "=f"(v.w) : "l"(p));
    return v;
}
__device__ __forceinline__ void bar_arrive(unsigned int* p) {
    asm volatile("red.release.gpu.global.add.u32 [%0], 1;" :: "l"(p) : "memory");
}
__device__ __forceinline__ unsigned int ld_acq(const unsigned int* p) {
    unsigned int v;
    asm volatile("ld.acquire.gpu.global.u32 %0, [%1];" : "=r"(v) : "l"(p) : "memory");
    return v;
}

// ---------------- cluster / mbarrier helpers --------------------------------
__device__ __forceinline__ uint32_t smem_u32(const void* p) {
    return (uint32_t)__cvta_generic_to_shared(p);
}
__device__ __forceinline__ void mbar_init(uint32_t a, uint32_t cnt) {
    asm volatile("mbarrier.init.shared.b64 [%0], %1;" :: "r"(a), "r"(cnt) : "memory");
}
// arrive (release, cluster scope) on the same-offset mbarrier in all 16 CTAs
__device__ __forceinline__ void arrive_all16(uint32_t a) {
    #pragma unroll
    for (int r = 0; r < 16; r++) {
        uint32_t ra;
        asm("mapa.shared::cluster.u32 %0, %1, %2;" : "=r"(ra) : "r"(a), "r"(r));
        asm volatile("mbarrier.arrive.release.cluster.shared::cluster.b64 _, [%0];"
                     :: "r"(ra) : "memory");
    }
}
__device__ __forceinline__ void mbar_wait(uint32_t a, uint32_t par) {
    asm volatile(
        "{\n\t.reg .pred P;\n"
        "W%=:\n\t"
        "mbarrier.try_wait.parity.acquire.cluster.shared::cta.b64 P, [%0], %1;\n\t"
        "@P bra D%=;\n\t"
        "bra W%=;\n"
        "D%=:\n\t}"
        :: "r"(a), "r"(par) : "memory");
}
// push one float to the same smem offset in all 16 cluster CTAs
__device__ __forceinline__ void push16(uint32_t a, float v) {
    #pragma unroll
    for (int r = 0; r < 16; r++) {
        uint32_t ra;
        asm("mapa.shared::cluster.u32 %0, %1, %2;" : "=r"(ra) : "r"(a), "r"(r));
        asm volatile("st.shared::cluster.f32 [%0], %1;" :: "r"(ra), "f"(v) : "memory");
    }
}
#define CLUSTER_SYNC() do { \
    asm volatile("barrier.cluster.arrive.aligned;" ::: "memory"); \
    asm volatile("barrier.cluster.wait.aligned;" ::: "memory"); } while (0)

__device__ __forceinline__ float sigmoid_f(float x) {
    return 1.0f / (1.0f + __expf(-x));
}
__device__ __forceinline__ float tanh_f(float x) {
    return 1.0f - 2.0f / (__expf(2.0f * x) + 1.0f);
}

// ============================================================================
// Phase 1: input projections (unchanged from R2; also resets fallback ctrs)
// ============================================================================
__global__ __launch_bounds__(256) void proj_kernel(
    const float* __restrict__ X,
    const float* __restrict__ Wf, const float* __restrict__ bf,
    const float* __restrict__ Wh, const float* __restrict__ bh)
{
    if (blockIdx.x == 0 && blockIdx.y == 0 && blockIdx.z == 0 && threadIdx.x < N_GROUPS)
        g_cnt[threadIdx.x * 32] = 0u;

    const float* W  = blockIdx.z ? Wh : Wf;
    const float* bv = blockIdx.z ? bh : bf;
    float* out = blockIdx.z ? g_xh : g_xf;

    __shared__ float As[16][132];
    __shared__ float Bs[16][68];

    const int tid = threadIdx.x;
    const int tx = tid & 15;
    const int ty = tid >> 4;
    const long m0 = (long)blockIdx.x * 128;
    const int  n0 = blockIdx.y * 64;

    u64 acc[4][4];
    #pragma unroll
    for (int p = 0; p < 4; p++)
        #pragma unroll
        for (int c = 0; c < 4; c++) acc[p][c] = 0ull;

    for (int k0 = 0; k0 < IDIM; k0 += 16) {
        #pragma unroll
        for (int q0 = 0; q0 < 2; q0++) {
            int q = tid + q0 * 256;
            int row = q >> 2;
            int kc  = (q & 3) * 4;
            float4 v = *(const float4*)&X[(m0 + row) * IDIM + k0 + kc];
            As[kc+0][row] = v.x; As[kc+1][row] = v.y;
            As[kc+2][row] = v.z; As[kc+3][row] = v.w;
        }
        {
            int row = tid >> 2;
            int kc  = (tid & 3) * 4;
            float4 v = *(const float4*)&W[(n0 + row) * IDIM + k0 + kc];
            Bs[kc+0][row] = v.x; Bs[kc+1][row] = v.y;
            Bs[kc+2][row] = v.z; Bs[kc+3][row] = v.w;
        }
        __syncthreads();

        #pragma unroll
        for (int kk = 0; kk < 16; kk++) {
            float4 a0 = *(const float4*)&As[kk][ty * 8];
            float4 a1 = *(const float4*)&As[kk][ty * 8 + 4];
            float4 b4 = *(const float4*)&Bs[kk][tx * 4];
            u64 a2[4] = { pack2(a0.x, a0.y), pack2(a0.z, a0.w),
                          pack2(a1.x, a1.y), pack2(a1.z, a1.w) };
            u64 bb[4] = { pack2(b4.x, b4.x), pack2(b4.y, b4.y),
                          pack2(b4.z, b4.z), pack2(b4.w, b4.w) };
            #pragma unroll
            for (int p = 0; p < 4; p++)
                #pragma unroll
                for (int c = 0; c < 4; c++)
                    acc[p][c] = ffma2(a2[p], bb[c], acc[p][c]);
        }
        __syncthreads();
    }

    float4 bias4 = *(const float4*)&bv[n0 + tx * 4];
    #pragma unroll
    for (int p = 0; p < 4; p++) {
        float2 c0 = unpack2(acc[p][0]);
        float2 c1 = unpack2(acc[p][1]);
        float2 c2 = unpack2(acc[p][2]);
        float2 c3 = unpack2(acc[p][3]);
        long mlo = m0 + ty * 8 + 2 * p;
        float4 lo = make_float4(c0.x + bias4.x, c1.x + bias4.y,
                                c2.x + bias4.z, c3.x + bias4.w);
        float4 hi = make_float4(c0.y + bias4.x, c1.y + bias4.y,
                                c2.y + bias4.z, c3.y + bias4.w);
        *(float4*)&out[mlo * HDIM + n0 + tx * 4]       = lo;
        *(float4*)&out[(mlo + 1) * HDIM + n0 + tx * 4] = hi;
    }
}

// ============================================================================
// Phase 2 (primary): cluster-16 persistent scan with DSMEM push exchange,
// dual-chain (4+4 batch rows) pipelining, weights register-resident.
// ============================================================================
__global__ __launch_bounds__(256, 1) void scan_cluster(
    const float* __restrict__ h0,
    const float* __restrict__ Whf,
    const float* __restrict__ Whh,
    float* __restrict__ out)
{
    __shared__ float h_s[8 * 512];
    __shared__ float g_s[8 * 512];
    __shared__ float part0[4 * 8 * 32];
    __shared__ float part1[4 * 8 * 32];
    __shared__ __align__(8) u64 mbar[4];   // g0, g1, h0, h1

    const int tid = threadIdx.x;
    const int blk = blockIdx.x & 15;       // cluster rank
    const int grp = blockIdx.x >> 4;
    const int j0  = blk * COLS_PER_BLK;
    const int b0  = grp * B_PER_GROUP;

    // GEMM mapping: (column j, k-slice ks of 64)
    const int j  = tid & 31;
    const int ks = tid >> 5;
    const int kb = ks * 64;
    // finalize mapping: chain chn (0/1), row fb (0..3), column fj
    const int chn = tid >> 7;
    const int fb  = (tid >> 5) & 3;
    const int fj  = tid & 31;
    const int frow = chn * 4 + fb;          // 0..7 within group

    // ---- weights: register-resident slices (32 float4 = 128 regs) ----
    float4 wf[16], wh[16];
    #pragma unroll
    for (int i = 0; i < 16; i++)
        wf[i] = *(const float4*)&Whf[(j0 + j) * HDIM + kb + 4 * i];
    #pragma unroll
    for (int i = 0; i < 16; i++)
        wh[i] = *(const float4*)&Whh[(j0 + j) * HDIM + kb + 4 * i];

    // ---- initial h (all 8 rows, full 512 cols, local copy) ----
    {
        const float4* src = (const float4*)&h0[b0 * HDIM];
        float4* dst = (float4*)h_s;
        for (int i = tid; i < 1024; i += 256) dst[i] = src[i];
    }
    if (tid == 0) {
        #pragma unroll
        for (int i = 0; i < 4; i++) mbar_init(smem_u32(&mbar[i]), 16);
    }
    __syncthreads();
    CLUSTER_SYNC();     // mbarrier inits visible cluster-wide before any push

    const uint32_t bar_g0 = smem_u32(&mbar[0]);
    const uint32_t bar_g1 = smem_u32(&mbar[1]);
    const uint32_t bar_h0 = smem_u32(&mbar[2]);
    const uint32_t bar_h1 = smem_u32(&mbar[3]);

    // per-thread push targets (same offset in every CTA)
    const uint32_t g_addr = smem_u32(&g_s[frow * 512 + j0 + fj]);
    const uint32_t h_addr = smem_u32(&h_s[frow * 512 + j0 + fj]);

    // register-carried per-thread state (own column of own rows)
    float hp = h_s[frow * 512 + j0 + fj];
    float f_reg = 0.0f;

    float* partA = chn ? part1 : part0;     // the part buffer this thread finalizes

    for (int t = 0; t < T_STEPS; t++) {
        const long xoff = (long)t * (BATCH * HDIM) + (long)(b0 + frow) * HDIM + j0 + fj;
        const float xf_v = __ldcs(&g_xf[xoff]);
        const float xh_v = __ldcs(&g_xh[xoff]);
        const uint32_t par  = t & 1;
        const uint32_t parp = (t - 1) & 1;

        // ---------------- A0: f-gate GEMM, chain 0 (rows 0..3) --------------
        {
            u64 acc[4] = {0ull, 0ull, 0ull, 0ull};
            #pragma unroll
            for (int i = 0; i < 16; i++) {
                u64 wlo = pack2(wf[i].x, wf[i].y);
                u64 whi = pack2(wf[i].z, wf[i].w);
                #pragma unroll
                for (int b = 0; b < 4; b++) {
                    float4 h4 = *(const float4*)&h_s[b * 512 + kb + 4 * i];
                    acc[b] = ffma2(wlo, pack2(h4.x, h4.y), acc[b]);
                    acc[b] = ffma2(whi, pack2(h4.z, h4.w), acc[b]);
                }
            }
            #pragma unroll
            for (int b = 0; b < 4; b++) {
                float2 a = unpack2(acc[b]);
                part0[(b * 8 + ks) * 32 + j] = a.x + a.y;
            }
        }
        __syncthreads();
        if (chn == 0) {                     // finalize A0 + push g0
            float s = xf_v;
            #pragma unroll
            for (int q = 0; q < 8; q++) s += part0[(fb * 8 + q) * 32 + fj];
            f_reg = sigmoid_f(s);
            push16(g_addr, f_reg * hp);
        }
        __syncthreads();
        if (tid == 0) arrive_all16(bar_g0);
        if (t > 0) mbar_wait(bar_h1, parp); // h rows 4..7 from prev step

        // ---------------- A1: f-gate GEMM, chain 1 (rows 4..7) --------------
        {
            u64 acc[4] = {0ull, 0ull, 0ull, 0ull};
            #pragma unroll
            for (int i = 0; i < 16; i++) {
                u64 wlo = pack2(wf[i].x, wf[i].y);
                u64 whi = pack2(wf[i].z, wf[i].w);
                #pragma unroll
                for (int b = 0; b < 4; b++) {
                    float4 h4 = *(const float4*)&h_s[(4 + b) * 512 + kb + 4 * i];
                    acc[b] = ffma2(wlo, pack2(h4.x, h4.y), acc[b]);
                    acc[b] = ffma2(whi, pack2(h4.z, h4.w), acc[b]);
                }
            }
            #pragma unroll
            for (int b = 0; b < 4; b++) {
                float2 a = unpack2(acc[b]);
                part1[(b * 8 + ks) * 32 + j] = a.x + a.y;
            }
        }
        __syncthreads();
        if (chn == 1) {                     // finalize A1 + push g1
            float s = xf_v;
            #pragma unroll
            for (int q = 0; q < 8; q++) s += part1[(fb * 8 + q) * 32 + fj];
            f_reg = sigmoid_f(s);
            push16(g_addr, f_reg * hp);
        }
        __syncthreads();
        if (tid == 0) arrive_all16(bar_g1);
        mbar_wait(bar_g0, par);

        // ---------------- B0: candidate GEMM, chain 0 ------------------------
        {
            u64 acc[4] = {0ull, 0ull, 0ull, 0ull};
            #pragma unroll
            for (int i = 0; i < 16; i++) {
                u64 wlo = pack2(wh[i].x, wh[i].y);
                u64 whi = pack2(wh[i].z, wh[i].w);
                #pragma unroll
                for (int b = 0; b < 4; b++) {
                    float4 g4 = *(const float4*)&g_s[b * 512 + kb + 4 * i];
                    acc[b] = ffma2(wlo, pack2(g4.x, g4.y), acc[b]);
                    acc[b] = ffma2(whi, pack2(g4.z, g4.w), acc[b]);
                }
            }
            #pragma unroll
            for (int b = 0; b < 4; b++) {
                float2 a = unpack2(acc[b]);
                part0[(b * 8 + ks) * 32 + j] = a.x + a.y;
            }
        }
        __syncthreads();
        if (chn == 0) {                     // finalize B0: blend + push h0
            float s = xh_v;
            #pragma unroll
            for (int q = 0; q < 8; q++) s += part0[(fb * 8 + q) * 32 + fj];
            float ht = tanh_f(s);
            float hn = fmaf(f_reg, ht - hp, hp);
            __stcs(&out[((long)t * BATCH + (b0 + frow)) * HDIM + j0 + fj], hn);
            if (t == T_STEPS - 1)
                out[(long)T_STEPS * BATCH * HDIM + (b0 + frow) * HDIM + j0 + fj] = hn;
            hp = hn;
            push16(h_addr, hn);
        }
        __syncthreads();
        if (tid == 0) arrive_all16(bar_h0);
        mbar_wait(bar_g1, par);

        // ---------------- B1: candidate GEMM, chain 1 ------------------------
        {
            u64 acc[4] = {0ull, 0ull, 0ull, 0ull};
            #pragma unroll
            for (int i = 0; i < 16; i++) {
                u64 wlo = pack2(wh[i].x, wh[i].y);
                u64 whi = pack2(wh[i].z, wh[i].w);
                #pragma unroll
                for (int b = 0; b < 4; b++) {
                    float4 g4 = *(const float4*)&g_s[(4 + b) * 512 + kb + 4 * i];
                    acc[b] = ffma2(wlo, pack2(g4.x, g4.y), acc[b]);
                    acc[b] = ffma2(whi, pack2(g4.z, g4.w), acc[b]);
                }
            }
            #pragma unroll
            for (int b = 0; b < 4; b++) {
                float2 a = unpack2(acc[b]);
                part1[(b * 8 + ks) * 32 + j] = a.x + a.y;
            }
        }
        __syncthreads();
        if (chn == 1) {                     // finalize B1: blend + push h1
            float s = xh_v;
            #pragma unroll
            for (int q = 0; q < 8; q++) s += part1[(fb * 8 + q) * 32 + fj];
            float ht = tanh_f(s);
            float hn = fmaf(f_reg, ht - hp, hp);
            __stcs(&out[((long)t * BATCH + (b0 + frow)) * HDIM + j0 + fj], hn);
            if (t == T_STEPS - 1)
                out[(long)T_STEPS * BATCH * HDIM + (b0 + frow) * HDIM + j0 + fj] = hn;
            hp = hn;
            push16(h_addr, hn);
        }
        __syncthreads();
        if (tid == 0) arrive_all16(bar_h1);
        mbar_wait(bar_h0, par);             // h rows 0..3 ready for next A0
    }

    CLUSTER_SYNC();     // keep CTAs alive until all inbound pushes/arrives land
}

// ============================================================================
// Phase 2 (fallback): R2 global-atomic scan (used if 16-CTA clusters fail)
// ============================================================================
#define WPAD 516
#define SCAN_SMEM ((2*32*WPAD + 8*512 + 8*512 + 8*8*32 + 8*32) * 4)

__global__ __launch_bounds__(256, 1) void scan_fallback(
    const float* __restrict__ h0,
    const float* __restrict__ Whf,
    const float* __restrict__ Whh,
    float* __restrict__ out)
{
    extern __shared__ float smem[];
    float* Wf_s  = smem;
    float* Wh_s  = Wf_s + 32 * WPAD;
    float* h_s   = Wh_s + 32 * WPAD;
    float* g_s   = h_s + 8 * 512;
    float* part  = g_s + 8 * 512;
    float* f_s   = part + 8 * 8 * 32;

    const int tid = threadIdx.x;
    const int grp = blockIdx.x >> 4;
    const int blk = blockIdx.x & 15;
    const int j0  = blk * COLS_PER_BLK;
    const int b0  = grp * B_PER_GROUP;

    const int j  = tid & 31;
    const int ks = tid >> 5;
    const int fb = tid >> 5;
    const int fj = tid & 31;

    for (int i = tid; i < 32 * 512; i += 256) {
        int r = i >> 9, c = i & 511;
        Wf_s[r * WPAD + c] = Whf[(j0 + r) * HDIM + c];
        Wh_s[r * WPAD + c] = Whh[(j0 + r) * HDIM + c];
    }
    {
        const float4* src = (const float4*)&h0[b0 * HDIM];
        float4* dst = (float4*)h_s;
        for (int i = tid; i < (8 * 512) / 4; i += 256) dst[i] = src[i];
    }
    __syncthreads();

    unsigned int* cntp = &g_cnt[grp * 32];
    unsigned int target = 0;
    const int kb = ks * 64;
    const float* wfrow = &Wf_s[j * WPAD + kb];
    const float* whrow = &Wh_s[j * WPAD + kb];

    for (int t = 0; t < T_STEPS; t++) {
        const long xbase = (long)t * (BATCH * HDIM) + (long)(b0 + fb) * HDIM + j0 + fj;
        const float xf_v = __ldcs(&g_xf[xbase]);
        const float xh_v = __ldcs(&g_xh[xbase]);

        {
            u64 acc[8];
            #pragma unroll
            for (int b = 0; b < 8; b++) acc[b] = 0ull;
            #pragma unroll
            for (int i = 0; i < 16; i++) {
                float4 w4 = *(const float4*)(wfrow + 4 * i);
                u64 wlo = pack2(w4.x, w4.y);
                u64 whi = pack2(w4.z, w4.w);
                #pragma unroll
                for (int b = 0; b < 8; b++) {
                    float4 h4 = *(const float4*)&h_s[b * 512 + kb + 4 * i];
                    acc[b] = ffma2(wlo, pack2(h4.x, h4.y), acc[b]);
                    acc[b] = ffma2(whi, pack2(h4.z, h4.w), acc[b]);
                }
            }
            #pragma unroll
            for (int b = 0; b < 8; b++) {
                float2 a = unpack2(acc[b]);
                part[(b * 8 + ks) * 32 + j] = a.x + a.y;
            }
        }
        __syncthreads();
        {
            float s = xf_v;
            #pragma unroll
            for (int q = 0; q < 8; q++) s += part[(fb * 8 + q) * 32 + fj];
            float f = sigmoid_f(s);
            f_s[fb * 32 + fj] = f;
            float g = f * h_s[fb * 512 + j0 + fj];
            g_gbuf[(b0 + fb) * HDIM + j0 + fj] = g;
        }
        __syncthreads();
        if (tid == 0) {
            bar_arrive(cntp);
            target += BLKS_PER_GROUP;
            while (ld_acq(cntp) < target) { }
        } else {
            target += BLKS_PER_GROUP;
        }
        __syncthreads();
        {
            const float4* src = (const float4*)&g_gbuf[b0 * HDIM];
            float4* dst = (float4*)g_s;
            #pragma unroll
            for (int q = 0; q < 4; q++) dst[tid + q * 256] = ldcg4(&src[tid + q * 256]);
        }
        __syncthreads();
        {
            u64 acc[8];
            #pragma unroll
            for (int b = 0; b < 8; b++) acc[b] = 0ull;
            #pragma unroll
            for (int i = 0; i < 16; i++) {
                float4 w4 = *(const float4*)(whrow + 4 * i);
                u64 wlo = pack2(w4.x, w4.y);
                u64 whi = pack2(w4.z, w4.w);
                #pragma unroll
                for (int b = 0; b < 8; b++) {
                    float4 g4 = *(const float4*)&g_s[b * 512 + kb + 4 * i];
                    acc[b] = ffma2(wlo, pack2(g4.x, g4.y), acc[b]);
                    acc[b] = ffma2(whi, pack2(g4.z, g4.w), acc[b]);
                }
            }
            #pragma unroll
            for (int b = 0; b < 8; b++) {
                float2 a = unpack2(acc[b]);
                part[(b * 8 + ks) * 32 + j] = a.x + a.y;
            }
        }
        __syncthreads();
        {
            float s = xh_v;
            #pragma unroll
            for (int q = 0; q < 8; q++) s += part[(fb * 8 + q) * 32 + fj];
            float ht = tanh_f(s);
            float f  = f_s[fb * 32 + fj];
            float hpv = h_s[fb * 512 + j0 + fj];
            float hn = fmaf(f, ht - hpv, hpv);
            out[((long)t * BATCH + (b0 + fb)) * HDIM + j0 + fj] = hn;
            g_hbuf[(b0 + fb) * HDIM + j0 + fj] = hn;
            if (t == T_STEPS - 1) {
                out[(long)T_STEPS * BATCH * HDIM + (b0 + fb) * HDIM + j0 + fj] = hn;
            }
        }
        __syncthreads();
        if (tid == 0) {
            bar_arrive(cntp);
            target += BLKS_PER_GROUP;
            while (ld_acq(cntp) < target) { }
        } else {
            target += BLKS_PER_GROUP;
        }
        __syncthreads();
        {
            const float4* src = (const float4*)&g_hbuf[b0 * HDIM];
            float4* dst = (float4*)h_s;
            #pragma unroll
            for (int q = 0; q < 4; q++) dst[tid + q * 256] = ldcg4(&src[tid + q * 256]);
        }
        __syncthreads();
    }
}

// ============================================================================
extern "C" void kernel_launch(void* const* d_in, const int* in_sizes, int n_in,
                              void* d_out, int out_size)
{
    const float* x   = (const float*)d_in[0];
    const float* h0  = (const float*)d_in[1];
    const float* Wxf = (const float*)d_in[2];
    const float* Whf = (const float*)d_in[3];
    const float* bf  = (const float*)d_in[4];
    const float* Wxh = (const float*)d_in[5];
    const float* Whh = (const float*)d_in[6];
    const float* bh  = (const float*)d_in[7];
    float* out = (float*)d_out;

    cudaFuncSetAttribute(scan_cluster,
                         cudaFuncAttributeNonPortableClusterSizeAllowed, 1);
    cudaFuncSetAttribute(scan_fallback,
                         cudaFuncAttributeMaxDynamicSharedMemorySize, SCAN_SMEM);

    dim3 pgrid((T_STEPS * BATCH) / 128, HDIM / 64, 2);
    proj_kernel<<<pgrid, 256>>>(x, Wxf, bf, Wxh, bh);

    // try the cluster-16 path; fall back to the proven global-atomic scan
    cudaLaunchConfig_t cfg = {};
    cfg.gridDim = dim3(N_GROUPS * BLKS_PER_GROUP, 1, 1);
    cfg.blockDim = dim3(256, 1, 1);
    cfg.dynamicSmemBytes = 0;
    cfg.stream = 0;
    cudaLaunchAttribute attrs[1];
    attrs[0].id = cudaLaunchAttributeClusterDimension;
    attrs[0].val.clusterDim.x = 16;
    attrs[0].val.clusterDim.y = 1;
    attrs[0].val.clusterDim.z = 1;
    cfg.attrs = attrs;
    cfg.numAttrs = 1;

    int nclusters = 0;
    cudaError_t qe = cudaOccupancyMaxActiveClusters(&nclusters, scan_cluster, &cfg);
    if (qe == cudaSuccess && nclusters >= N_GROUPS) {
        cudaLaunchKernelEx(&cfg, scan_cluster, h0, Whf, Whh, out);
    } else {
        cudaGetLastError();   // clear sticky query error
        scan_fallback<<<N_GROUPS * BLKS_PER_GROUP, 256, SCAN_SMEM>>>(h0, Whf, Whh, out);
    }
}